// round 14
// baseline (speedup 1.0000x reference)
#include <cuda_runtime.h>

#define FULLMASK 0xffffffffu
typedef unsigned long long ull;

// ---------- packed f32x2 helpers (Blackwell sm_103a) ----------
__device__ __forceinline__ ull pk2(float a, float b) {
    ull r;
    asm("mov.b64 %0, {%1, %2};" : "=l"(r) : "f"(a), "f"(b));
    return r;
}
__device__ __forceinline__ float2 upk2(ull v) {
    float2 r;
    asm("mov.b64 {%0, %1}, %2;" : "=f"(r.x), "=f"(r.y) : "l"(v));
    return r;
}
__device__ __forceinline__ ull dup2(float a) { return pk2(a, a); }

__device__ __forceinline__ ull ffma2(ull a, ull b, ull c) {
    ull d;
    asm("fma.rn.f32x2 %0, %1, %2, %3;" : "=l"(d) : "l"(a), "l"(b), "l"(c));
    return d;
}
__device__ __forceinline__ ull add2(ull a, ull b) {
    ull d;
    asm("add.rn.f32x2 %0, %1, %2;" : "=l"(d) : "l"(a), "l"(b));
    return d;
}

// HW tanh: single MUFU.TANH (sm_75+), abs err ~1e-5
__device__ __forceinline__ float tanh_hw(float z) {
    float r;
    asm("tanh.approx.f32 %0, %1;" : "=f"(r) : "f"(z));
    return r;
}

// float->int via magic number (valid |v| < 2^22): FADD + IADD, replaces F2I cvt
#define MAGIC_F 12582912.0f          // 1.5 * 2^23
__device__ __forceinline__ int f2i_magic(float v) {
    return __float_as_int(v + MAGIC_F) - __float_as_int(MAGIC_F);
}

// warp sum of 2^23-scaled values: magic f2i -> redux.s32 -> full-range cvt back
__device__ __forceinline__ float redux_scaled(float gp_scaled) {
    int si;
    const int gi = f2i_magic(gp_scaled);
    asm("redux.sync.add.s32 %0, %1, 0xffffffff;" : "=r"(si) : "r"(gi));
    float sf;
    asm("cvt.rn.f32.s32 %0, %1;" : "=f"(sf) : "r"(si));
    return sf;
}

// Best skeleton (R12): 1024 single-warp CTAs, 2 elements/warp.
// Lane l owns h1 units (2l,2l+1) and layer-2 cols (l,l+32); W2 in 128 regs;
// SEPARATE per-element layer-2 loops (fusing them costs regs — measured).
// R14: magic f2i in the redux chain, dtn*2^-23 hoisted off-chain, unroll 4.
__global__ void __launch_bounds__(32)
maxwell_ffnn_kernel(const float* __restrict__ x,
                    const float* __restrict__ W1,
                    const float* __restrict__ b1,
                    const float* __restrict__ W2,
                    const float* __restrict__ b2,
                    const float* __restrict__ W3,
                    const float* __restrict__ b3,
                    float* __restrict__ out) {
    __shared__ __align__(16) ull hbuf[2][2][32];   // [parity][elem][lane]

    const int l  = threadIdx.x & 31;
    const int jA = l;
    const int jB = l + 32;
    const int u0 = 2 * l;

    const float SC = 8388608.0f;               // 2^23 (redux scale)
    const float IS = 1.1920928955078125e-7f;   // 2^-23

    // ---- loop-invariant weights in registers ----
    const ull c1a = pk2(__ldg(&W1[u0]),      __ldg(&W1[u0 + 1]));
    const ull c1b = pk2(__ldg(&W1[64 + u0]), __ldg(&W1[64 + u0 + 1]));
    const ull cb1 = pk2(__ldg(&b1[u0]),      __ldg(&b1[u0 + 1]));

    ull w2A[32], w2B[32];
#pragma unroll
    for (int s = 0; s < 32; ++s) {
        w2A[s] = pk2(__ldg(&W2[(2 * s) * 64 + jA]),
                     __ldg(&W2[(2 * s + 1) * 64 + jA]));
        w2B[s] = pk2(__ldg(&W2[(2 * s) * 64 + jB]),
                     __ldg(&W2[(2 * s + 1) * 64 + jB]));
    }
    const float b2A = __ldg(&b2[jA]);
    const float b2B = __ldg(&b2[jB]);
    const float w3A = SC * __ldg(&W3[jA]);     // 2^23 * W3 (for integer redux)
    const float w3B = SC * __ldg(&W3[jB]);
    const float b3v = __ldg(&b3[0]);

    const float2* xp0 = (const float2*)(x + (size_t)(blockIdx.x * 2) * 2048);
    const float2* xp1 = xp0 + 1024;
    float* op0 = out + (size_t)(blockIdx.x * 2) * 1024;
    float* op1 = op0 + 1024;

    float gamma0 = 0.0f, gamma1 = 0.0f;
    float2 xv0 = __ldg(&xp0[0]);
    float2 xv1 = __ldg(&xp1[0]);
    const ull zero2 = pk2(0.0f, 0.0f);

#pragma unroll 4
    for (int t = 0; t < 1024; ++t) {
        const int par = t & 1;
        const float eps0 = xv0.x, dtn0 = xv0.y;
        const float eps1 = xv1.x, dtn1 = xv1.y;
        if (t < 1023) { xv0 = __ldg(&xp0[t + 1]); xv1 = __ldg(&xp1[t + 1]); }

        // off-chain folds (computed while nothing depends on them)
        const float gpre0 = fmaf(dtn0, b3v, gamma0);   // gamma + dtn*b3
        const float gpre1 = fmaf(dtn1, b3v, gamma1);
        const float dIS0  = dtn0 * IS;                 // dtn * 2^-23
        const float dIS1  = dtn1 * IS;

        // ---- layer 1 (both elements): 2 ffma2 + 2 MUFU.TANH each ----
        {
            const ull p0 = ffma2(dup2(gamma0), c1b, ffma2(dup2(eps0), c1a, cb1));
            const ull p1 = ffma2(dup2(gamma1), c1b, ffma2(dup2(eps1), c1a, cb1));
            const float2 q0 = upk2(p0);
            const float2 q1 = upk2(p1);
            hbuf[par][0][l] = pk2(tanh_hw(q0.x), tanh_hw(q0.y));
            hbuf[par][1][l] = pk2(tanh_hw(q1.x), tanh_hw(q1.y));
        }
        __syncwarp();

        // ---- layer 2 + 3 partial (both elements, SEPARATE loops, depth-8) ----
        float gp[2];
#pragma unroll
        for (int e = 0; e < 2; ++e) {
            const ulonglong2* hp = (const ulonglong2*)&hbuf[par][e][0];
            ull A0 = pk2(b2A, 0.0f), A1 = zero2, A2 = zero2, A3 = zero2;
            ull B0 = pk2(b2B, 0.0f), B1 = zero2, B2 = zero2, B3 = zero2;
#pragma unroll
            for (int k = 0; k < 8; ++k) {
                const ulonglong2 ha = hp[2 * k];
                const ulonglong2 hb = hp[2 * k + 1];
                A0 = ffma2(ha.x, w2A[4 * k],     A0);
                B0 = ffma2(ha.x, w2B[4 * k],     B0);
                A1 = ffma2(ha.y, w2A[4 * k + 1], A1);
                B1 = ffma2(ha.y, w2B[4 * k + 1], B1);
                A2 = ffma2(hb.x, w2A[4 * k + 2], A2);
                B2 = ffma2(hb.x, w2B[4 * k + 2], B2);
                A3 = ffma2(hb.y, w2A[4 * k + 3], A3);
                B3 = ffma2(hb.y, w2B[4 * k + 3], B3);
            }
            const float2 aA = upk2(add2(add2(A0, A1), add2(A2, A3)));
            const float2 aB = upk2(add2(add2(B0, B1), add2(B2, B3)));
            // scaled by 2^23 via w3A/w3B for the integer redux
            gp[e] = fmaf(tanh_hw(aA.x + aA.y), w3A,
                         tanh_hw(aB.x + aB.y) * w3B);
        }

        // ---- warp sums: magic f2i + single-instruction redux per element ----
        const float s0 = redux_scaled(gp[0]);
        const float s1 = redux_scaled(gp[1]);

        // ---- gamma update + output ----
        gamma0 = fmaf(dIS0, s0, gpre0);
        gamma1 = fmaf(dIS1, s1, gpre1);

        // sigma = 0.5*eps + 2*(eps - gamma) = 2.5*eps - 2*gamma
        if (l == 0) op0[t] = fmaf(-2.0f, gamma0, 2.5f * eps0);
        if (l == 1) op1[t] = fmaf(-2.0f, gamma1, 2.5f * eps1);
    }
}

extern "C" void kernel_launch(void* const* d_in, const int* in_sizes, int n_in,
                              void* d_out, int out_size) {
    (void)in_sizes; (void)n_in; (void)out_size;
    const float* x  = (const float*)d_in[0];
    const float* W1 = (const float*)d_in[1];
    const float* b1 = (const float*)d_in[2];
    const float* W2 = (const float*)d_in[3];
    const float* b2 = (const float*)d_in[4];
    const float* W3 = (const float*)d_in[5];
    const float* b3 = (const float*)d_in[6];
    float* out = (float*)d_out;

    // 2 elements per warp: 1024 single-warp CTAs (~7/SM, single wave)
    maxwell_ffnn_kernel<<<1024, 32>>>(x, W1, b1, W2, b2, W3, b3, out);
}

// round 15
// speedup vs baseline: 1.0437x; 1.0437x over previous
#include <cuda_runtime.h>

#define FULLMASK 0xffffffffu
typedef unsigned long long ull;

// ---------- packed f32x2 helpers (Blackwell sm_103a) ----------
__device__ __forceinline__ ull pk2(float a, float b) {
    ull r;
    asm("mov.b64 %0, {%1, %2};" : "=l"(r) : "f"(a), "f"(b));
    return r;
}
__device__ __forceinline__ float2 upk2(ull v) {
    float2 r;
    asm("mov.b64 {%0, %1}, %2;" : "=f"(r.x), "=f"(r.y) : "l"(v));
    return r;
}
__device__ __forceinline__ ull dup2(float a) { return pk2(a, a); }

__device__ __forceinline__ ull ffma2(ull a, ull b, ull c) {
    ull d;
    asm("fma.rn.f32x2 %0, %1, %2, %3;" : "=l"(d) : "l"(a), "l"(b), "l"(c));
    return d;
}
__device__ __forceinline__ ull add2(ull a, ull b) {
    ull d;
    asm("add.rn.f32x2 %0, %1, %2;" : "=l"(d) : "l"(a), "l"(b));
    return d;
}

// HW tanh: single MUFU.TANH (sm_75+), abs err ~1e-5
__device__ __forceinline__ float tanh_hw(float z) {
    float r;
    asm("tanh.approx.f32 %0, %1;" : "=f"(r) : "f"(z));
    return r;
}

// float->int via magic number (valid |v| < 2^22): FADD + IADD, replaces F2I cvt
#define MAGIC_F 12582912.0f          // 1.5 * 2^23
__device__ __forceinline__ int f2i_magic(float v) {
    return __float_as_int(v + MAGIC_F) - __float_as_int(MAGIC_F);
}

// warp sum of 2^23-scaled values: magic f2i -> redux.s32 -> full-range cvt back
__device__ __forceinline__ float redux_scaled(float gp_scaled) {
    int si;
    const int gi = f2i_magic(gp_scaled);
    asm("redux.sync.add.s32 %0, %1, 0xffffffff;" : "=r"(si) : "r"(gi));
    float sf;
    asm("cvt.rn.f32.s32 %0, %1;" : "=f"(sf) : "r"(si));
    return sf;
}

// R12 skeleton EXACTLY (1024 single-warp CTAs, 2 elems/warp, unroll 2 — body
// fits L0 I$; separate per-element layer-2 loops) with only the two chain
// cuts kept from R14: magic f2i in the redux path, dtn*2^-23 hoisted.
__global__ void __launch_bounds__(32)
maxwell_ffnn_kernel(const float* __restrict__ x,
                    const float* __restrict__ W1,
                    const float* __restrict__ b1,
                    const float* __restrict__ W2,
                    const float* __restrict__ b2,
                    const float* __restrict__ W3,
                    const float* __restrict__ b3,
                    float* __restrict__ out) {
    __shared__ __align__(16) ull hbuf[2][2][32];   // [parity][elem][lane]

    const int l  = threadIdx.x & 31;
    const int jA = l;
    const int jB = l + 32;
    const int u0 = 2 * l;

    const float SC = 8388608.0f;               // 2^23 (redux scale)
    const float IS = 1.1920928955078125e-7f;   // 2^-23

    // ---- loop-invariant weights in registers ----
    const ull c1a = pk2(__ldg(&W1[u0]),      __ldg(&W1[u0 + 1]));
    const ull c1b = pk2(__ldg(&W1[64 + u0]), __ldg(&W1[64 + u0 + 1]));
    const ull cb1 = pk2(__ldg(&b1[u0]),      __ldg(&b1[u0 + 1]));

    ull w2A[32], w2B[32];
#pragma unroll
    for (int s = 0; s < 32; ++s) {
        w2A[s] = pk2(__ldg(&W2[(2 * s) * 64 + jA]),
                     __ldg(&W2[(2 * s + 1) * 64 + jA]));
        w2B[s] = pk2(__ldg(&W2[(2 * s) * 64 + jB]),
                     __ldg(&W2[(2 * s + 1) * 64 + jB]));
    }
    const float b2A = __ldg(&b2[jA]);
    const float b2B = __ldg(&b2[jB]);
    const float w3A = SC * __ldg(&W3[jA]);     // 2^23 * W3 (for integer redux)
    const float w3B = SC * __ldg(&W3[jB]);
    const float b3v = __ldg(&b3[0]);

    const float2* xp0 = (const float2*)(x + (size_t)(blockIdx.x * 2) * 2048);
    const float2* xp1 = xp0 + 1024;
    float* op0 = out + (size_t)(blockIdx.x * 2) * 1024;
    float* op1 = op0 + 1024;

    float gamma0 = 0.0f, gamma1 = 0.0f;
    float2 xv0 = __ldg(&xp0[0]);
    float2 xv1 = __ldg(&xp1[0]);
    const ull zero2 = pk2(0.0f, 0.0f);

#pragma unroll 2
    for (int t = 0; t < 1024; ++t) {
        const int par = t & 1;
        const float eps0 = xv0.x, dtn0 = xv0.y;
        const float eps1 = xv1.x, dtn1 = xv1.y;
        if (t < 1023) { xv0 = __ldg(&xp0[t + 1]); xv1 = __ldg(&xp1[t + 1]); }

        // off-chain folds (computed while nothing depends on them)
        const float gpre0 = fmaf(dtn0, b3v, gamma0);   // gamma + dtn*b3
        const float gpre1 = fmaf(dtn1, b3v, gamma1);
        const float dIS0  = dtn0 * IS;                 // dtn * 2^-23
        const float dIS1  = dtn1 * IS;

        // ---- layer 1 (both elements): 2 ffma2 + 2 MUFU.TANH each ----
        {
            const ull p0 = ffma2(dup2(gamma0), c1b, ffma2(dup2(eps0), c1a, cb1));
            const ull p1 = ffma2(dup2(gamma1), c1b, ffma2(dup2(eps1), c1a, cb1));
            const float2 q0 = upk2(p0);
            const float2 q1 = upk2(p1);
            hbuf[par][0][l] = pk2(tanh_hw(q0.x), tanh_hw(q0.y));
            hbuf[par][1][l] = pk2(tanh_hw(q1.x), tanh_hw(q1.y));
        }
        __syncwarp();

        // ---- layer 2 + 3 partial (both elements, SEPARATE loops, depth-8) ----
        float gp[2];
#pragma unroll
        for (int e = 0; e < 2; ++e) {
            const ulonglong2* hp = (const ulonglong2*)&hbuf[par][e][0];
            ull A0 = pk2(b2A, 0.0f), A1 = zero2, A2 = zero2, A3 = zero2;
            ull B0 = pk2(b2B, 0.0f), B1 = zero2, B2 = zero2, B3 = zero2;
#pragma unroll
            for (int k = 0; k < 8; ++k) {
                const ulonglong2 ha = hp[2 * k];
                const ulonglong2 hb = hp[2 * k + 1];
                A0 = ffma2(ha.x, w2A[4 * k],     A0);
                B0 = ffma2(ha.x, w2B[4 * k],     B0);
                A1 = ffma2(ha.y, w2A[4 * k + 1], A1);
                B1 = ffma2(ha.y, w2B[4 * k + 1], B1);
                A2 = ffma2(hb.x, w2A[4 * k + 2], A2);
                B2 = ffma2(hb.x, w2B[4 * k + 2], B2);
                A3 = ffma2(hb.y, w2A[4 * k + 3], A3);
                B3 = ffma2(hb.y, w2B[4 * k + 3], B3);
            }
            const float2 aA = upk2(add2(add2(A0, A1), add2(A2, A3)));
            const float2 aB = upk2(add2(add2(B0, B1), add2(B2, B3)));
            // scaled by 2^23 via w3A/w3B for the integer redux
            gp[e] = fmaf(tanh_hw(aA.x + aA.y), w3A,
                         tanh_hw(aB.x + aB.y) * w3B);
        }

        // ---- warp sums: magic f2i + single-instruction redux per element ----
        const float s0 = redux_scaled(gp[0]);
        const float s1 = redux_scaled(gp[1]);

        // ---- gamma update + output ----
        gamma0 = fmaf(dIS0, s0, gpre0);
        gamma1 = fmaf(dIS1, s1, gpre1);

        // sigma = 0.5*eps + 2*(eps - gamma) = 2.5*eps - 2*gamma
        if (l == 0) op0[t] = fmaf(-2.0f, gamma0, 2.5f * eps0);
        if (l == 1) op1[t] = fmaf(-2.0f, gamma1, 2.5f * eps1);
    }
}

extern "C" void kernel_launch(void* const* d_in, const int* in_sizes, int n_in,
                              void* d_out, int out_size) {
    (void)in_sizes; (void)n_in; (void)out_size;
    const float* x  = (const float*)d_in[0];
    const float* W1 = (const float*)d_in[1];
    const float* b1 = (const float*)d_in[2];
    const float* W2 = (const float*)d_in[3];
    const float* b2 = (const float*)d_in[4];
    const float* W3 = (const float*)d_in[5];
    const float* b3 = (const float*)d_in[6];
    float* out = (float*)d_out;

    // 2 elements per warp: 1024 single-warp CTAs (~7/SM, single wave)
    maxwell_ffnn_kernel<<<1024, 32>>>(x, W1, b1, W2, b2, W3, b3, out);
}